// round 2
// baseline (speedup 1.0000x reference)
#include <cuda_runtime.h>
#include <stdint.h>
#include <math.h>

#define ND 96      // node dim
#define ED 64      // edge dim
#define KD 256     // in dim
#define TE 32      // edges per tile
#define BLK 384    // threads per block
#define MAXN (1<<17)

typedef unsigned long long u64t;

__device__ float g_cnt[MAXN];
__device__ int g_is64;

__device__ __forceinline__ uint32_t smem_u32(const void* p) {
    uint32_t r;
    asm("{ .reg .u64 t; cvta.to.shared.u64 t, %1; cvt.u32.u64 %0, t; }"
        : "=r"(r) : "l"(p));
    return r;
}

__global__ void init_kernel(float* __restrict__ out, const uint32_t* __restrict__ ew,
                            long long total, int n, long long nwords) {
    long long i = (long long)blockIdx.x * blockDim.x + threadIdx.x;
    if (i < total) out[i] = 0.0f;
    if (i < n) g_cnt[i] = 0.0f;
    if (i == 0) {
        // int64 vs int32 edge_index detection: for int64 (values < 2^31),
        // every odd 32-bit word (high half) is zero.
        int is64 = 1;
        long long m = nwords < 256 ? nwords : 256;
        for (long long w = 1; w < m; w += 2)
            if (ew[w] != 0u) { is64 = 0; break; }
        g_is64 = is64;
    }
}

__global__ __launch_bounds__(BLK, 1)
void edge_kernel(const float* __restrict__ h,
                 const void* __restrict__ eidx,
                 const float* __restrict__ edge_attr,
                 const float* __restrict__ W_e, const float* __restrict__ b_e,
                 const float* __restrict__ W_n, const float* __restrict__ b_n,
                 float* __restrict__ out, int E, int ntiles) {
    extern __shared__ float smem[];
    float* sW = smem;                 // KD*2*ND floats: [k][2j]=We[k][j], [k][2j+1]=Wn[k][j]
    float* sx = smem + KD * 2 * ND;   // KD*TE floats, 128B rows, chunk-swizzled; reused as redbuf/gbuf
    int*   sI = (int*)(sx + KD * TE); // [2*TE]: src[0:TE), dst[TE:2TE)

    const int tid = threadIdx.x;
    const int j   = tid % ND;         // output column
    const int sub = tid / ND;         // 0..3
    const int g   = sub & 1;          // edge half: edges [16g, 16g+16)
    const int kh  = sub >> 1;         // k half:    k in [128*kh, 128*kh+128)
    const int tid0 = g * ND + j;      // 0..191

    // Load both weight matrices into smem, interleaved per (k,j).
    for (int idx = tid; idx < KD * ND; idx += BLK) {
        int k = idx / ND, c = idx % ND;
        sW[k * 2 * ND + 2 * c]     = W_e[idx];
        sW[k * 2 * ND + 2 * c + 1] = W_n[idx];
    }

    const int is64 = g_is64;
    const long long* e64 = (const long long*)eidx;
    const int*       e32 = (const int*)eidx;

    const uint32_t sx_b = smem_u32(sx);
    const float be = b_e[j], bn = b_n[j];

    u64t*  redbuf = (u64t*)sx;
    float* gbuf   = sx;

    for (int t = blockIdx.x; t < ntiles; t += gridDim.x) {
        long long ebase = (long long)t * TE;
        __syncthreads();  // sx/sI free from previous tile (and covers W-load on iter 0)

        if (tid < 2 * TE) {
            int which = tid >> 5;  // 0 = src, 1 = dst (TE == 32)
            int e = tid & 31;
            long long eg = ebase + e;
            int v = -1;
            if (eg < (long long)E) {
                long long pos = (long long)which * E + eg;
                v = is64 ? (int)e64[pos] : e32[pos];
            }
            sI[tid] = v;
        }
        __syncthreads();

        // Stage x[e][k] into swizzled smem rows (row = 32 floats = 128B).
        #pragma unroll 4
        for (int idx = tid; idx < TE * KD; idx += BLK) {
            int e = idx >> 8;
            int k = idx & (KD - 1);
            float v = 0.0f;
            int src = sI[e];
            if (src >= 0) {
                if (k < ND)            v = h[(long long)src * ND + k];
                else if (k < 2 * ND)   v = h[(long long)sI[TE + e] * ND + (k - ND)];
                else                   v = edge_attr[ebase * ED + (long long)e * ED + (k - 2 * ND)];
            }
            int chunk = (e >> 2) ^ (k & 7);
            sx[k * TE + chunk * 4 + (e & 3)] = v;
        }
        __syncthreads();

        // Main GEMM fragment: acc[a] covers edges (16g+2a, 16g+2a+1), both matrices,
        // partial over this thread's k-half. Packed f32x2 FMAs.
        u64t aE[8], aN[8];
        #pragma unroll
        for (int a = 0; a < 8; a++) { aE[a] = 0ull; aN[a] = 0ull; }

        const float* wp = sW + 2 * j + (kh * 128) * (2 * ND);
        const uint32_t xb = sx_b + (uint32_t)(kh * 128) * (TE * 4);
        #pragma unroll 4
        for (int kk = 0; kk < 128; kk++) {
            float2 w = *(const float2*)(wp + kk * 2 * ND);
            u64t we2, wn2;
            asm("mov.b64 %0, {%1,%1};" : "=l"(we2) : "r"(__float_as_uint(w.x)));
            asm("mov.b64 %0, {%1,%1};" : "=l"(wn2) : "r"(__float_as_uint(w.y)));
            int sw = kk & 7;  // (kh*128 + kk) & 7 == kk & 7
            uint32_t rowb = xb + (uint32_t)kk * (TE * 4);
            #pragma unroll
            for (int i2 = 0; i2 < 4; i2++) {
                int chunk = (4 * g + i2) ^ sw;
                u64t x01, x23;
                asm("ld.shared.v2.b64 {%0,%1}, [%2];"
                    : "=l"(x01), "=l"(x23) : "r"(rowb + (uint32_t)chunk * 16));
                asm("fma.rn.f32x2 %0, %1, %2, %0;" : "+l"(aE[2 * i2])     : "l"(x01), "l"(we2));
                asm("fma.rn.f32x2 %0, %1, %2, %0;" : "+l"(aE[2 * i2 + 1]) : "l"(x23), "l"(we2));
                asm("fma.rn.f32x2 %0, %1, %2, %0;" : "+l"(aN[2 * i2])     : "l"(x01), "l"(wn2));
                asm("fma.rn.f32x2 %0, %1, %2, %0;" : "+l"(aN[2 * i2 + 1]) : "l"(x23), "l"(wn2));
            }
        }

        __syncthreads();  // x reads done; sx reusable as reduction buffer
        if (kh == 1) {
            #pragma unroll
            for (int a = 0; a < 8; a++) {
                redbuf[a * 192 + tid0]       = aE[a];
                redbuf[(8 + a) * 192 + tid0] = aN[a];
            }
        }
        __syncthreads();

        float gv[16];
        if (kh == 0) {
            #pragma unroll
            for (int a = 0; a < 8; a++) {
                u64t pe = redbuf[a * 192 + tid0];
                u64t pn = redbuf[(8 + a) * 192 + tid0];
                asm("add.rn.f32x2 %0, %0, %1;" : "+l"(aE[a]) : "l"(pe));
                asm("add.rn.f32x2 %0, %0, %1;" : "+l"(aN[a]) : "l"(pn));
                uint32_t el, eh, nl, nh;
                asm("mov.b64 {%0,%1}, %2;" : "=r"(el), "=r"(eh) : "l"(aE[a]));
                asm("mov.b64 {%0,%1}, %2;" : "=r"(nl), "=r"(nh) : "l"(aN[a]));
                float se0 = __uint_as_float(el) + be;
                float se1 = __uint_as_float(eh) + be;
                float sn0 = __uint_as_float(nl) + bn;
                float sn1 = __uint_as_float(nh) + bn;
                float g0 = 1.0f / (1.0f + expf(-se0));
                float g1 = 1.0f / (1.0f + expf(-se1));
                float m0 = fmaxf(sn0, 0.0f) + log1pf(expf(-fabsf(sn0)));
                float m1 = fmaxf(sn1, 0.0f) + log1pf(expf(-fabsf(sn1)));
                gv[2 * a]     = g0 * m0;
                gv[2 * a + 1] = g1 * m1;
            }
        }
        __syncthreads();  // all redbuf reads done before gbuf overwrites it
        if (kh == 0) {
            #pragma unroll
            for (int a = 0; a < 8; a++) {
                int e = 16 * g + 2 * a;
                gbuf[e * ND + j]       = gv[2 * a];
                gbuf[(e + 1) * ND + j] = gv[2 * a + 1];
            }
        }
        __syncthreads();

        // Scatter: 32 edges x 96 cols as float2 vector reductions.
        for (int q = tid; q < TE * ND / 2; q += BLK) {
            int e = q / (ND / 2);
            int c = (q % (ND / 2)) * 2;
            int dst = sI[TE + e];
            if (dst >= 0) {
                float2 v = *(const float2*)(gbuf + e * ND + c);
                float* addr = out + (long long)dst * ND + c;
                asm volatile("red.global.add.v2.f32 [%0], {%1,%2};"
                             :: "l"(addr), "f"(v.x), "f"(v.y) : "memory");
            }
        }
        if (tid < TE) {
            int dst = sI[TE + tid];
            if (dst >= 0) atomicAdd(&g_cnt[dst], 1.0f);
        }
    }
}

__global__ void finalize_kernel(const float* __restrict__ h, float* __restrict__ out,
                                long long total) {
    long long i = (long long)blockIdx.x * blockDim.x + threadIdx.x;
    if (i < total) {
        int node = (int)(i / ND);
        float c = g_cnt[node];
        c = c < 1.0f ? 1.0f : c;
        out[i] = h[i] + out[i] / c;
    }
}

extern "C" void kernel_launch(void* const* d_in, const int* in_sizes, int n_in,
                              void* d_out, int out_size) {
    const float* h   = (const float*)d_in[0];
    const void*  ei  = d_in[1];
    const float* ea  = (const float*)d_in[2];
    const float* W_e = (const float*)d_in[3];
    const float* b_e = (const float*)d_in[4];
    const float* W_n = (const float*)d_in[5];
    const float* b_n = (const float*)d_in[6];
    float* out = (float*)d_out;

    int N = in_sizes[0] / ND;
    int E = in_sizes[2] / ED;
    long long total  = (long long)N * ND;
    long long nwords = (long long)in_sizes[1];  // >= 2E 32-bit words either way

    int ib = (int)((total + 255) / 256);
    init_kernel<<<ib, 256>>>(out, (const uint32_t*)ei, total, N, nwords);

    int ntiles = (E + TE - 1) / TE;
    size_t shmem = (size_t)(KD * 2 * ND + KD * TE) * sizeof(float) + 2 * TE * sizeof(int);
    cudaFuncSetAttribute(edge_kernel, cudaFuncAttributeMaxDynamicSharedMemorySize, (int)shmem);
    int grid = 148 * 4;
    if (grid > ntiles) grid = ntiles;
    edge_kernel<<<grid, BLK, shmem>>>(h, ei, ea, W_e, b_e, W_n, b_n, out, E, ntiles);

    finalize_kernel<<<ib, 256>>>(h, out, total);
}

// round 4
// speedup vs baseline: 4.5833x; 4.5833x over previous
#include <cuda_runtime.h>
#include <cuda_bf16.h>
#include <stdint.h>
#include <math.h>

#define ND 96
#define ED 64
#define KD 256
#define TM 128          // edges per tile (MMA M)
#define NTOT 192        // fused output cols (We|Wn)
#define BLK 384
#define MAXN (1<<17)

__device__ float g_cnt[MAXN];
__device__ int g_is64;

// ---- smem layout ----
#define SB_OFF    0          // B tile: 192x256 bf16 blocked SW128  (98304)
#define SA_OFF    98304      // A tile: 128x256 bf16 blocked SW128  (65536)
#define SBIAS_OFF 163840     // 192 floats (768)
#define SI_OFF    164608     // src[128] + dst[128] ints (1024)
#define SMEM_REQ  165632

#define SW128(o) ((o) ^ (((o) >> 3) & 0x70))

__device__ __forceinline__ uint32_t smem_u32(const void* p) {
    uint32_t r;
    asm("{ .reg .u64 t; cvta.to.shared.u64 t, %1; cvt.u32.u64 %0, t; }"
        : "=r"(r) : "l"(p));
    return r;
}
__device__ __forceinline__ void ldsm_x4(uint32_t* r, uint32_t addr) {
    asm volatile("ldmatrix.sync.aligned.m8n8.x4.shared.b16 {%0,%1,%2,%3}, [%4];"
        : "=r"(r[0]), "=r"(r[1]), "=r"(r[2]), "=r"(r[3]) : "r"(addr));
}
__device__ __forceinline__ void ldsm_x2(uint32_t* r, uint32_t addr) {
    asm volatile("ldmatrix.sync.aligned.m8n8.x2.shared.b16 {%0,%1}, [%2];"
        : "=r"(r[0]), "=r"(r[1]) : "r"(addr));
}
__device__ __forceinline__ void mma16816(float* c, const uint32_t* a, const uint32_t* b) {
    asm volatile("mma.sync.aligned.m16n8k16.row.col.f32.bf16.bf16.f32 "
        "{%0,%1,%2,%3}, {%4,%5,%6,%7}, {%8,%9}, {%0,%1,%2,%3};"
        : "+f"(c[0]), "+f"(c[1]), "+f"(c[2]), "+f"(c[3])
        : "r"(a[0]), "r"(a[1]), "r"(a[2]), "r"(a[3]), "r"(b[0]), "r"(b[1]));
}

// ---------------- init / finalize ----------------
__global__ void init_kernel(float4* __restrict__ out4, const uint32_t* __restrict__ ew,
                            long long total4, int n, long long nwords) {
    long long i = (long long)blockIdx.x * blockDim.x + threadIdx.x;
    if (i < total4) out4[i] = make_float4(0.f, 0.f, 0.f, 0.f);
    if (i < n) g_cnt[i] = 0.0f;
    if (i == 0) {
        int is64 = 1;
        long long m = nwords < 256 ? nwords : 256;
        for (long long w = 1; w < m; w += 2)
            if (ew[w] != 0u) { is64 = 0; break; }
        g_is64 = is64;
    }
}

__global__ void finalize_kernel(const float4* __restrict__ h4, float4* __restrict__ out4,
                                long long total4) {
    long long i = (long long)blockIdx.x * blockDim.x + threadIdx.x;
    if (i < total4) {
        int node = (int)(i / (ND / 4));
        float c = g_cnt[node];
        c = c < 1.0f ? 1.0f : c;
        float inv = 1.0f / c;
        float4 a = h4[i], b = out4[i];
        out4[i] = make_float4(a.x + b.x * inv, a.y + b.y * inv,
                              a.z + b.z * inv, a.w + b.w * inv);
    }
}

// ---------------- main edge kernel ----------------
__global__ __launch_bounds__(BLK, 1)
void edge_kernel(const float* __restrict__ h,
                 const void* __restrict__ eidx,
                 const float* __restrict__ edge_attr,
                 const float* __restrict__ W_e, const float* __restrict__ b_e,
                 const float* __restrict__ W_n, const float* __restrict__ b_n,
                 float* __restrict__ out, int E, int ntiles) {
    extern __shared__ char sm[];
    const uint32_t sbase = smem_u32(sm);

    const int tid = threadIdx.x;
    const int wid = tid >> 5;
    const int lane = tid & 31;
    const int wm = wid >> 2;          // 0..2 -> rows [64*wm .. not) -- wait 12 warps: wm 0..2? see below
    // 12 warps: wm = wid % 2? Use: wm = wid & 1 (2 row halves), wn = wid >> 1 (6 col slices of 16)
    const int wmr = wid & 1;          // row half: rows [64*wmr, 64*wmr+64)
    const int wnc = wid >> 1;         // 0..5: gate cols [16*wnc,16*wnc+16), msg cols 96+...

    // B tile: rows n<96 = W_e col n; n>=96 = W_n col n-96.  [n][k] bf16, blocked SW128.
    for (int idx = tid; idx < NTOT * (KD / 2); idx += BLK) {
        int n = idx >> 7;
        int k = (idx & 127) * 2;
        const float* W = (n < ND) ? W_e : W_n;
        int col = (n < ND) ? n : n - ND;
        float f0 = W[k * ND + col];
        float f1 = W[(k + 1) * ND + col];
        __nv_bfloat162 p = __floats2bfloat162_rn(f0, f1);
        uint32_t off = (uint32_t)(k >> 6) * 24576u + (uint32_t)(n >> 3) * 1024u
                     + (uint32_t)(n & 7) * 128u + (uint32_t)(k & 63) * 2u;
        *(uint32_t*)(sm + SB_OFF + SW128(off)) = *(uint32_t*)&p;
    }
    float* sBias = (float*)(sm + SBIAS_OFF);
    for (int j = tid; j < NTOT; j += BLK)
        sBias[j] = (j < ND) ? b_e[j] : b_n[j - ND];

    const int is64 = g_is64;
    const long long* e64 = (const long long*)eidx;
    const int*       e32 = (const int*)eidx;
    int* sI = (int*)(sm + SI_OFF);

    // --- per-lane ldmatrix address precomputation ---
    // A frag (x4): matrix m = lane>>3; e = e0 + (m&1)*8 + (lane&7); khalf = m>>1.
    const int a_m = lane >> 3;
    const int a_erow = ((a_m & 1) << 3) + (lane & 7);   // row within 16-row block
    const int a_khalf = a_m >> 1;
    // B frag gate/msg (x4 over 16 cols): n = n0 + (m&2)*4 + (lane&7); khalf = m&1.
    const int b_m = lane >> 3;
    const int b_nrow = ((b_m & 2) << 2) + (lane & 7);
    const int b_khalf = b_m & 1;

    const uint32_t saA = sbase + SA_OFF;
    const uint32_t saB = sbase + SB_OFF;

    const int grid = gridDim.x;
    const int bid = blockIdx.x;

    for (int t = bid; t < ntiles; t += grid) {
        long long ebase = (long long)t * TM;
        __syncthreads();   // prev tile fully consumed (A + sI)

        if (tid < 2 * TM) {
            int which = tid >> 7;
            int e = tid & 127;
            long long eg = ebase + e;
            int v = -1;
            if (eg < (long long)E) {
                long long pos = (long long)which * E + eg;
                v = is64 ? (int)e64[pos] : e32[pos];
            }
            sI[tid] = v;
        }
        __syncthreads();

        // gather + convert into A tile (blocked SW128, bf16)
        for (int idx = tid; idx < TM * (KD / 4); idx += BLK) {
            int e = idx >> 6;
            int k = (idx & 63) * 4;
            int src = sI[e];
            float4 x = make_float4(0.f, 0.f, 0.f, 0.f);
            if (src >= 0) {
                if (k < ND)
                    x = *(const float4*)(h + (long long)src * ND + k);
                else if (k < 2 * ND)
                    x = *(const float4*)(h + (long long)sI[TM + e] * ND + (k - ND));
                else
                    x = *(const float4*)(edge_attr + (ebase + e) * ED + (k - 2 * ND));
            }
            __nv_bfloat162 p0 = __floats2bfloat162_rn(x.x, x.y);
            __nv_bfloat162 p1 = __floats2bfloat162_rn(x.z, x.w);
            uint2 u = make_uint2(*(uint32_t*)&p0, *(uint32_t*)&p1);
            uint32_t off = (uint32_t)(k >> 6) * 16384u + (uint32_t)(e >> 3) * 1024u
                         + (uint32_t)(e & 7) * 128u + (uint32_t)(k & 63) * 2u;
            *(uint2*)(sm + SA_OFF + SW128(off)) = u;
        }
        if (tid < TM) {
            int d = sI[TM + tid];
            if (d >= 0) atomicAdd(&g_cnt[d], 1.0f);
        }
        __syncthreads();

        // ---- GEMM: warp tile = 64 rows x (16 gate + 16 msg) cols ----
        float cg[4][2][4], cmsg[4][2][4];
        #pragma unroll
        for (int i = 0; i < 4; i++)
            #pragma unroll
            for (int j = 0; j < 2; j++)
                #pragma unroll
                for (int c = 0; c < 4; c++) { cg[i][j][c] = 0.f; cmsg[i][j][c] = 0.f; }

        // per-lane invariants
        uint32_t aBase[4], aSw[4];
        #pragma unroll
        for (int i = 0; i < 4; i++) {
            int e = 64 * wmr + 16 * i + a_erow;
            aBase[i] = saA + (uint32_t)(e >> 3) * 1024u + (uint32_t)(e & 7) * 128u;
            aSw[i] = (uint32_t)(e & 7);
        }
        int ng0 = 16 * wnc;
        int ng = ng0 + b_nrow;             // gate col row for this lane
        int nm = ng + ND;                  // msg col row
        uint32_t bgBase = saB + (uint32_t)(ng >> 3) * 1024u + (uint32_t)(ng & 7) * 128u;
        uint32_t bgSw = (uint32_t)(ng & 7);
        uint32_t bmBase = saB + (uint32_t)(nm >> 3) * 1024u + (uint32_t)(nm & 7) * 128u;
        uint32_t bmSw = (uint32_t)(nm & 7);

        #pragma unroll 4
        for (int kc = 0; kc < 16; kc++) {
            uint32_t kblkA = (uint32_t)(kc >> 2) * 16384u;
            uint32_t kblkB = (uint32_t)(kc >> 2) * 24576u;
            uint32_t kc2 = (uint32_t)((kc & 3) << 1);

            uint32_t aF[4][4];
            #pragma unroll
            for (int i = 0; i < 4; i++) {
                uint32_t chunk = ((kc2 | (uint32_t)a_khalf) ^ aSw[i]) << 4;
                ldsm_x4(aF[i], kblkA + aBase[i] + chunk);
            }
            uint32_t bg[4], bm[4];
            {
                uint32_t cg_ = ((kc2 | (uint32_t)b_khalf) ^ bgSw) << 4;
                ldsm_x4(bg, kblkB + bgBase + cg_);
                uint32_t cm_ = ((kc2 | (uint32_t)b_khalf) ^ bmSw) << 4;
                ldsm_x4(bm, kblkB + bmBase + cm_);
            }
            #pragma unroll
            for (int i = 0; i < 4; i++) {
                mma16816(cg[i][0], aF[i], bg);
                mma16816(cg[i][1], aF[i], bg + 2);
                mma16816(cmsg[i][0], aF[i], bm);
                mma16816(cmsg[i][1], aF[i], bm + 2);
            }
        }

        // ---- epilogue: register-local gate*message, scatter ----
        const int g = lane >> 2;
        const int tt = lane & 3;
        #pragma unroll
        for (int i = 0; i < 4; i++) {
            int row0 = 64 * wmr + 16 * i + g;
            int row1 = row0 + 8;
            int dst0 = sI[TM + row0];
            int dst1 = sI[TM + row1];
            #pragma unroll
            for (int j = 0; j < 2; j++) {
                int col = ng0 + 8 * j + 2 * tt;
                float bg0 = sBias[col], bg1 = sBias[col + 1];
                float bn0 = sBias[ND + col], bn1 = sBias[ND + col + 1];
                float* G = cg[i][j];
                float* M = cmsg[i][j];
                #pragma unroll
                for (int hhalf = 0; hhalf < 2; hhalf++) {
                    float xg0 = G[2 * hhalf] + bg0;
                    float xg1 = G[2 * hhalf + 1] + bg1;
                    float xn0 = M[2 * hhalf] + bn0;
                    float xn1 = M[2 * hhalf + 1] + bn1;
                    float gate0 = __fdividef(1.0f, 1.0f + __expf(-xg0));
                    float gate1 = __fdividef(1.0f, 1.0f + __expf(-xg1));
                    float sp0 = fmaxf(xn0, 0.0f) + __logf(1.0f + __expf(-fabsf(xn0)));
                    float sp1 = fmaxf(xn1, 0.0f) + __logf(1.0f + __expf(-fabsf(xn1)));
                    float v0 = gate0 * sp0;
                    float v1 = gate1 * sp1;
                    int dst = hhalf ? dst1 : dst0;
                    if (dst >= 0) {
                        asm volatile("red.global.add.v2.f32 [%0], {%1,%2};"
                            :: "l"(out + (long long)dst * ND + col), "f"(v0), "f"(v1)
                            : "memory");
                    }
                }
            }
        }
    }
}

extern "C" void kernel_launch(void* const* d_in, const int* in_sizes, int n_in,
                              void* d_out, int out_size) {
    const float* h   = (const float*)d_in[0];
    const void*  ei  = d_in[1];
    const float* ea  = (const float*)d_in[2];
    const float* W_e = (const float*)d_in[3];
    const float* b_e = (const float*)d_in[4];
    const float* W_n = (const float*)d_in[5];
    const float* b_n = (const float*)d_in[6];
    float* out = (float*)d_out;

    int N = in_sizes[0] / ND;
    int E = in_sizes[2] / ED;
    long long total4 = (long long)N * ND / 4;
    long long nwords = (long long)in_sizes[1];

    int ib = (int)((total4 + 255) / 256);
    init_kernel<<<ib, 256>>>((float4*)out, (const uint32_t*)ei, total4, N, nwords);

    int ntiles = (E + TM - 1) / TM;
    cudaFuncSetAttribute(edge_kernel, cudaFuncAttributeMaxDynamicSharedMemorySize, SMEM_REQ);
    int grid = ntiles < 148 ? ntiles : 148;
    edge_kernel<<<grid, BLK, SMEM_REQ>>>(h, ei, ea, W_e, b_e, W_n, b_n, out, E, ntiles);

    finalize_kernel<<<ib, 256>>>((const float4*)h, (float4*)out, total4);
}

// round 5
// speedup vs baseline: 4.7196x; 1.0297x over previous
#include <cuda_runtime.h>
#include <cuda_bf16.h>
#include <stdint.h>
#include <math.h>

#define ND 96
#define ED 64
#define KD 256
#define TM 128          // edges per tile (MMA M)
#define NTOT 192        // fused output cols (We|Wn)
#define BLK 384
#define MAXN (1<<17)

__device__ float g_cnt[MAXN];
__device__ int g_is64;

// ---- smem layout (exactly 227 KB) ----
#define SB_OFF   0          // B tile: 192x256 bf16 blocked SW128 (98304)
#define SA0_OFF  98304      // A tile buf0: 128x256 bf16 (65536)
#define SA1_OFF  163840     // A tile buf1: 65536
#define SI_OFF   229376     // 3 x (src[128]+dst[128]) ints (3072)
#define SMEM_REQ 232448

#define SW128(o) ((o) ^ (((o) >> 3) & 0x70))

__device__ __forceinline__ uint32_t smem_u32(const void* p) {
    uint32_t r;
    asm("{ .reg .u64 t; cvta.to.shared.u64 t, %1; cvt.u32.u64 %0, t; }"
        : "=r"(r) : "l"(p));
    return r;
}
__device__ __forceinline__ void ldsm_x4(uint32_t* r, uint32_t addr) {
    asm volatile("ldmatrix.sync.aligned.m8n8.x4.shared.b16 {%0,%1,%2,%3}, [%4];"
        : "=r"(r[0]), "=r"(r[1]), "=r"(r[2]), "=r"(r[3]) : "r"(addr));
}
__device__ __forceinline__ void mma16816(float* c, const uint32_t* a, const uint32_t* b) {
    asm volatile("mma.sync.aligned.m16n8k16.row.col.f32.bf16.bf16.f32 "
        "{%0,%1,%2,%3}, {%4,%5,%6,%7}, {%8,%9}, {%0,%1,%2,%3};"
        : "+f"(c[0]), "+f"(c[1]), "+f"(c[2]), "+f"(c[3])
        : "r"(a[0]), "r"(a[1]), "r"(a[2]), "r"(a[3]), "r"(b[0]), "r"(b[1]));
}

// ---------------- init / finalize ----------------
__global__ void init_kernel(float4* __restrict__ out4, const uint32_t* __restrict__ ew,
                            long long total4, int n, long long nwords) {
    long long i = (long long)blockIdx.x * blockDim.x + threadIdx.x;
    if (i < total4) out4[i] = make_float4(0.f, 0.f, 0.f, 0.f);
    if (i < n) g_cnt[i] = 0.0f;
    if (i == 0) {
        int is64 = 1;
        long long m = nwords < 256 ? nwords : 256;
        for (long long w = 1; w < m; w += 2)
            if (ew[w] != 0u) { is64 = 0; break; }
        g_is64 = is64;
    }
}

__global__ void finalize_kernel(const float4* __restrict__ h4, float4* __restrict__ out4,
                                long long total4) {
    long long i = (long long)blockIdx.x * blockDim.x + threadIdx.x;
    if (i < total4) {
        int node = (int)(i / (ND / 4));
        float c = g_cnt[node];
        c = c < 1.0f ? 1.0f : c;
        float inv = 1.0f / c;
        float4 a = h4[i], b = out4[i];
        out4[i] = make_float4(a.x + b.x * inv, a.y + b.y * inv,
                              a.z + b.z * inv, a.w + b.w * inv);
    }
}

// ---------------- staging helpers ----------------
__device__ __forceinline__ void stage_idx(int* sIb, long long ebase, int E, int is64,
                                          const long long* e64, const int* e32, int tid) {
    if (tid < 2 * TM) {
        int which = tid >> 7;
        int e = tid & 127;
        long long eg = ebase + e;
        int v = -1;
        if (eg < (long long)E) {
            long long pos = (long long)which * E + eg;
            v = is64 ? (int)e64[pos] : e32[pos];
        }
        sIb[tid] = v;
        if (which && v >= 0) atomicAdd(&g_cnt[v], 1.0f);
    }
}

__device__ __forceinline__ void gather_tile(char* sm, uint32_t aoff, const int* sIb,
                                            long long ebase, const float* __restrict__ h,
                                            const float* __restrict__ edge_attr, int tid) {
    #pragma unroll 4
    for (int idx = tid; idx < TM * (KD / 4); idx += BLK) {
        int e = idx >> 6;
        int k = (idx & 63) * 4;
        int src = sIb[e];
        float4 x = make_float4(0.f, 0.f, 0.f, 0.f);
        if (src >= 0) {
            if (k < ND)
                x = *(const float4*)(h + (long long)src * ND + k);
            else if (k < 2 * ND)
                x = *(const float4*)(h + (long long)sIb[TM + e] * ND + (k - ND));
            else
                x = *(const float4*)(edge_attr + (ebase + e) * ED + (k - 2 * ND));
        }
        __nv_bfloat162 p0 = __floats2bfloat162_rn(x.x, x.y);
        __nv_bfloat162 p1 = __floats2bfloat162_rn(x.z, x.w);
        uint2 u = make_uint2(*(uint32_t*)&p0, *(uint32_t*)&p1);
        uint32_t off = (uint32_t)(k >> 6) * 16384u + (uint32_t)(e >> 3) * 1024u
                     + (uint32_t)(e & 7) * 128u + (uint32_t)(k & 63) * 2u;
        *(uint2*)(sm + aoff + SW128(off)) = u;
    }
}

__device__ __forceinline__ float act_gm(float xg, float xn) {
    float gate = __fdividef(1.0f, 1.0f + __expf(-xg));
    float sp = fmaxf(xn, 0.0f) + __logf(1.0f + __expf(-fabsf(xn)));
    return gate * sp;
}

// ---------------- main edge kernel ----------------
__global__ __launch_bounds__(BLK, 1)
void edge_kernel(const float* __restrict__ h,
                 const void* __restrict__ eidx,
                 const float* __restrict__ edge_attr,
                 const float* __restrict__ W_e, const float* __restrict__ b_e,
                 const float* __restrict__ W_n, const float* __restrict__ b_n,
                 float* __restrict__ out, int E, int ntiles) {
    extern __shared__ char sm[];
    const uint32_t sbase = smem_u32(sm);

    const int tid = threadIdx.x;
    const int wid = tid >> 5;
    const int lane = tid & 31;
    const int wmr = wid & 1;          // row half: rows [64*wmr, 64*wmr+64)
    const int wnc = wid >> 1;         // 0..5: gate cols [16*wnc,+16), msg cols +96

    // B tile: rows n<96 = W_e col n; n>=96 = W_n col n-96.  [n][k] bf16, blocked SW128.
    for (int idx = tid; idx < NTOT * (KD / 2); idx += BLK) {
        int n = idx >> 7;
        int k = (idx & 127) * 2;
        const float* W = (n < ND) ? W_e : W_n;
        int col = (n < ND) ? n : n - ND;
        float f0 = W[k * ND + col];
        float f1 = W[(k + 1) * ND + col];
        __nv_bfloat162 p = __floats2bfloat162_rn(f0, f1);
        uint32_t off = (uint32_t)(k >> 6) * 24576u + (uint32_t)(n >> 3) * 1024u
                     + (uint32_t)(n & 7) * 128u + (uint32_t)(k & 63) * 2u;
        *(uint32_t*)(sm + SB_OFF + SW128(off)) = *(uint32_t*)&p;
    }

    // per-lane bias registers (cols fixed per lane)
    const int tt = lane & 3;
    float bgc[2][2], bnc[2][2];
    #pragma unroll
    for (int j = 0; j < 2; j++) {
        int c0 = 16 * wnc + 8 * j + 2 * tt;
        bgc[j][0] = b_e[c0];     bgc[j][1] = b_e[c0 + 1];
        bnc[j][0] = b_n[c0];     bnc[j][1] = b_n[c0 + 1];
    }

    const int is64 = g_is64;
    const long long* e64 = (const long long*)eidx;
    const int*       e32 = (const int*)eidx;
    int* sI = (int*)(sm + SI_OFF);   // 3-deep ring, 256 ints each

    // --- per-lane ldmatrix constants ---
    const int a_m = lane >> 3;
    const int a_erow = ((a_m & 1) << 3) + (lane & 7);
    const int a_khalf = a_m >> 1;
    const int b_m = lane >> 3;
    const int b_nrow = ((b_m & 2) << 2) + (lane & 7);
    const int b_khalf = b_m & 1;

    const uint32_t saB = sbase + SB_OFF;
    const int ng0 = 16 * wnc;
    const int ng = ng0 + b_nrow;
    const int nm = ng + ND;
    const uint32_t bgBase = saB + (uint32_t)(ng >> 3) * 1024u + (uint32_t)(ng & 7) * 128u;
    const uint32_t bgSw = (uint32_t)(ng & 7);
    const uint32_t bmBase = saB + (uint32_t)(nm >> 3) * 1024u + (uint32_t)(nm & 7) * 128u;
    const uint32_t bmSw = (uint32_t)(nm & 7);

    const int grid = gridDim.x;
    const int bid = blockIdx.x;
    const int nloc = (ntiles - bid + grid - 1) / grid;

    // ---- prologue: stage tile 0 (+ idx for tile 1) ----
    stage_idx(sI, (long long)bid * TM, E, is64, e64, e32, tid);
    __syncthreads();
    gather_tile(sm, SA0_OFF, sI, (long long)bid * TM, h, edge_attr, tid);
    if (nloc > 1)
        stage_idx(sI + 256, (long long)(bid + grid) * TM, E, is64, e64, e32, tid);
    __syncthreads();

    const int gg = lane >> 2;
    const int ttOdd = tt & 1;

    for (int L = 0; L < nloc; L++) {
        const int buf = L & 1;
        const int* sIL = sI + (L % 3) * 256;
        const uint32_t saAb = sbase + (buf ? SA1_OFF : SA0_OFF);

        // dst registers for epilogue (read before any future sI writes to this slot)
        int dstA[4], dstB[4];
        #pragma unroll
        for (int i = 0; i < 4; i++) {
            int row0 = 64 * wmr + 16 * i + gg;
            dstA[i] = sIL[TM + row0];
            dstB[i] = sIL[TM + row0 + 8];
        }

        // ---- GEMM: warp tile = 64 rows x (16 gate + 16 msg) cols ----
        float cg[4][2][4], cmsg[4][2][4];
        #pragma unroll
        for (int i = 0; i < 4; i++)
            #pragma unroll
            for (int j = 0; j < 2; j++)
                #pragma unroll
                for (int c = 0; c < 4; c++) { cg[i][j][c] = 0.f; cmsg[i][j][c] = 0.f; }

        uint32_t aBase[4], aSw[4];
        #pragma unroll
        for (int i = 0; i < 4; i++) {
            int e = 64 * wmr + 16 * i + a_erow;
            aBase[i] = saAb + (uint32_t)(e >> 3) * 1024u + (uint32_t)(e & 7) * 128u;
            aSw[i] = (uint32_t)(e & 7);
        }

        #pragma unroll 4
        for (int kc = 0; kc < 16; kc++) {
            uint32_t kblkA = (uint32_t)(kc >> 2) * 16384u;
            uint32_t kblkB = (uint32_t)(kc >> 2) * 24576u;
            uint32_t kc2 = (uint32_t)((kc & 3) << 1);

            uint32_t aF[4][4];
            #pragma unroll
            for (int i = 0; i < 4; i++) {
                uint32_t chunk = ((kc2 | (uint32_t)a_khalf) ^ aSw[i]) << 4;
                ldsm_x4(aF[i], kblkA + aBase[i] + chunk);
            }
            uint32_t bg[4], bm[4];
            {
                uint32_t cg_ = ((kc2 | (uint32_t)b_khalf) ^ bgSw) << 4;
                ldsm_x4(bg, kblkB + bgBase + cg_);
                uint32_t cm_ = ((kc2 | (uint32_t)b_khalf) ^ bmSw) << 4;
                ldsm_x4(bm, kblkB + bmBase + cm_);
            }
            #pragma unroll
            for (int i = 0; i < 4; i++) {
                mma16816(cg[i][0], aF[i], bg);
                mma16816(cg[i][1], aF[i], bg + 2);
                mma16816(cmsg[i][0], aF[i], bm);
                mma16816(cmsg[i][1], aF[i], bm + 2);
            }
        }

        // ---- stage next tile while HMMA drains ----
        if (L + 1 < nloc) {
            long long ebase1 = (long long)(bid + (L + 1) * grid) * TM;
            gather_tile(sm, buf ? SA0_OFF : SA1_OFF, sI + ((L + 1) % 3) * 256,
                        ebase1, h, edge_attr, tid);
            if (L + 2 < nloc)
                stage_idx(sI + ((L + 2) % 3) * 256, (long long)(bid + (L + 2) * grid) * TM,
                          E, is64, e64, e32, tid);
        }

        // ---- epilogue: activations + v4 scatter via butterfly exchange ----
        #pragma unroll
        for (int i = 0; i < 4; i++) {
            int dst0 = dstA[i], dst1 = dstB[i];
            #pragma unroll
            for (int j = 0; j < 2; j++) {
                float v00 = act_gm(cg[i][j][0] + bgc[j][0], cmsg[i][j][0] + bnc[j][0]);
                float v01 = act_gm(cg[i][j][1] + bgc[j][1], cmsg[i][j][1] + bnc[j][1]);
                float v10 = act_gm(cg[i][j][2] + bgc[j][0], cmsg[i][j][2] + bnc[j][0]);
                float v11 = act_gm(cg[i][j][3] + bgc[j][1], cmsg[i][j][3] + bnc[j][1]);
                // even tt lanes keep row0 (send row1); odd keep row1 (send row0)
                float s0 = ttOdd ? v00 : v10;
                float s1 = ttOdd ? v01 : v11;
                float r0 = __shfl_xor_sync(0xffffffffu, s0, 1);
                float r1 = __shfl_xor_sync(0xffffffffu, s1, 1);
                int colbase = ng0 + 8 * j + (tt >> 1) * 4;
                if (!ttOdd) {
                    if (dst0 >= 0) {
                        asm volatile("red.global.add.v4.f32 [%0], {%1,%2,%3,%4};"
                            :: "l"(out + (long long)dst0 * ND + colbase),
                               "f"(v00), "f"(v01), "f"(r0), "f"(r1) : "memory");
                    }
                } else {
                    if (dst1 >= 0) {
                        asm volatile("red.global.add.v4.f32 [%0], {%1,%2,%3,%4};"
                            :: "l"(out + (long long)dst1 * ND + colbase),
                               "f"(r0), "f"(r1), "f"(v10), "f"(v11) : "memory");
                    }
                }
            }
        }

        __syncthreads();
    }
}

extern "C" void kernel_launch(void* const* d_in, const int* in_sizes, int n_in,
                              void* d_out, int out_size) {
    const float* h   = (const float*)d_in[0];
    const void*  ei  = d_in[1];
    const float* ea  = (const float*)d_in[2];
    const float* W_e = (const float*)d_in[3];
    const float* b_e = (const float*)d_in[4];
    const float* W_n = (const float*)d_in[5];
    const float* b_n = (const float*)d_in[6];
    float* out = (float*)d_out;

    int N = in_sizes[0] / ND;
    int E = in_sizes[2] / ED;
    long long total4 = (long long)N * ND / 4;
    long long nwords = (long long)in_sizes[1];

    int ib = (int)((total4 + 255) / 256);
    init_kernel<<<ib, 256>>>((float4*)out, (const uint32_t*)ei, total4, N, nwords);

    int ntiles = (E + TM - 1) / TM;
    cudaFuncSetAttribute(edge_kernel, cudaFuncAttributeMaxDynamicSharedMemorySize, SMEM_REQ);
    int grid = ntiles < 148 ? ntiles : 148;
    edge_kernel<<<grid, BLK, SMEM_REQ>>>(h, ei, ea, W_e, b_e, W_n, b_n, out, E, ntiles);

    finalize_kernel<<<ib, 256>>>((const float4*)h, (float4*)out, total4);
}